// round 9
// baseline (speedup 1.0000x reference)
#include <cuda_runtime.h>
#include <cuda_fp16.h>
#include <math.h>
#include <stdint.h>

// Problem constants: B=128, T=200, NC=3, NB=2, D=512, DH=256
#define NBOXES  153600
#define GPB     600
#define RPB     1800

// ---------------- scratch ----------------
// Compacted A (present boxes only): [slot][0:256) = fp16(a)
__device__ __half  g_A[(size_t)NBOXES * 256];
// B[n][0:256) = fp16(w2[k][n]) (K-major per n)
__device__ __half  g_B[512 * 256];
__device__ float4  g_meta[NBOXES];   // per slot: {float(m*4+cat), conf, cx, cy}
__device__ float   g_E[9 * 512];     // b2+confb+cb+catT[c]+cam[v]
__device__ float4  g_T4[512];        // {confw, cw0, cw1, miss}
__device__ int     g_cnt;            // number of present boxes (compacted rows)

// ---------------- helpers ----------------
__device__ __forceinline__ uint32_t smem_u32(const void* p) {
    uint32_t a;
    asm("{ .reg .u64 t; cvta.to.shared.u64 t, %1; cvt.u32.u64 %0, t; }" : "=r"(a) : "l"(p));
    return a;
}
__device__ __forceinline__ void cpasync16(uint32_t s, const void* g) {
    asm volatile("cp.async.cg.shared.global [%0], [%1], 16;" :: "r"(s), "l"(g));
}
#define CP_COMMIT() asm volatile("cp.async.commit_group;" ::: "memory")
#define CP_WAIT(n)  asm volatile("cp.async.wait_group %0;" :: "n"(n) : "memory")

__device__ __forceinline__ void ldm_x4(uint32_t* r, uint32_t addr) {
    asm volatile("ldmatrix.sync.aligned.m8n8.x4.shared.b16 {%0,%1,%2,%3}, [%4];"
        : "=r"(r[0]), "=r"(r[1]), "=r"(r[2]), "=r"(r[3]) : "r"(addr));
}
__device__ __forceinline__ void mma16816(float* d, const uint32_t* a, uint32_t b0, uint32_t b1) {
    asm volatile(
        "mma.sync.aligned.m16n8k16.row.col.f32.f16.f16.f32 "
        "{%0,%1,%2,%3}, {%4,%5,%6,%7}, {%8,%9}, {%0,%1,%2,%3};"
        : "+f"(d[0]), "+f"(d[1]), "+f"(d[2]), "+f"(d[3])
        : "r"(a[0]), "r"(a[1]), "r"(a[2]), "r"(a[3]), "r"(b0), "r"(b1));
}

// ============================================================
// Kernel AUX: w2 fp16 convert (blocks 0..511), epilogue tables
// (blocks 512..521), counter reset (block 522). 512 threads.
// ============================================================
__global__ void aux_kernel(
    const float* __restrict__ w2,
    const float* __restrict__ b2,    const float* __restrict__ catT,
    const float* __restrict__ confw, const float* __restrict__ confb,
    const float* __restrict__ cw,    const float* __restrict__ cb,
    const float* __restrict__ miss,  const float* __restrict__ cam)
{
    int blk = blockIdx.x;
    int t = threadIdx.x;
    if (blk < 512) {
        if (t < 256) {
            int n = blk, k = t;
            float x = __ldg(w2 + (size_t)k * 512 + n);
            g_B[(size_t)n * 256 + k] = __float2half(x);
        }
    } else if (blk < 521) {
        int e = blk - 512;
        int n = t;
        int c = e / 3, v = e % 3;
        g_E[e * 512 + n] = __ldg(b2 + n) + __ldg(confb + n) + __ldg(cb + n)
                         + __ldg(catT + c * 512 + n) + __ldg(cam + v * 512 + n);
    } else if (blk == 521) {
        int n = t;
        g_T4[n] = make_float4(__ldg(confw + n), __ldg(cw + n),
                              __ldg(cw + 512 + n), __ldg(miss + n));
    } else {
        if (t == 0) g_cnt = 0;
    }
}

// ============================================================
// Kernel A: per-GROUP prep (one warp per group of 2 boxes).
// Lanes 0-15 handle sorted box 0, lanes 16-31 sorted box 1.
// Each lane owns 16 hidden dims. Compaction into g_A; missing
// rows + dist rows written directly to out.
// ============================================================
__global__ void __launch_bounds__(256) prep_kernel(
    const float* __restrict__ box,
    const float* __restrict__ w1,  const float* __restrict__ b1,
    const float* __restrict__ lng, const float* __restrict__ lnb,
    const float* __restrict__ dw,  const float* __restrict__ db,
    const float* __restrict__ missv,
    float* __restrict__ out)
{
    __shared__ int s_pref[16];
    __shared__ int s_base;

    int wid  = threadIdx.x >> 5;
    int lane = threadIdx.x & 31;
    int grp  = blockIdx.x * 8 + wid;
    int half = lane >> 4;        // sorted position jj of this half-warp
    int hl   = lane & 15;

    const float* p = box + (size_t)grp * 12;
    float r0[6], r1[6];
#pragma unroll
    for (int i = 0; i < 6; i++) { r0[i] = __ldg(p + i); r1[i] = __ldg(p + 6 + i); }

    const float inw = 1.0f / 640.0f, inh = 1.0f / 400.0f;
    float c0x1 = r0[0]*inw, c0y1 = r0[1]*inh, c0x2 = r0[2]*inw, c0y2 = r0[3]*inh;
    float c1x1 = r1[0]*inw, c1y1 = r1[1]*inh, c1x2 = r1[2]*inw, c1y2 = r1[3]*inh;
    float s0 = c0x1 + c0y1 + c0x2 + c0y2;
    float s1 = c1x1 + c1y1 + c1x2 + c1y2;
    float pr0 = (s0 != 0.0f) ? 1.0f : 0.0f;
    float pr1 = (s1 != 0.0f) ? 1.0f : 0.0f;
    float k0 = r0[4] + (1.0f - pr0) * 1000.0f;
    float k1 = r1[4] + (1.0f - pr1) * 1000.0f;
    bool swp = (k1 < k0);                     // stable argsort of 2
    bool takeSecond = swp ? (half == 0) : (half == 1);

    float x1 = takeSecond ? c1x1 : c0x1;
    float y1 = takeSecond ? c1y1 : c0y1;
    float x2 = takeSecond ? c1x2 : c0x2;
    float y2 = takeSecond ? c1y2 : c0y2;
    float cat = takeSecond ? r1[4] : r0[4];
    float cf  = takeSecond ? r1[5] : r0[5];
    float pr  = takeSecond ? pr1  : pr0;
    bool present = (pr != 0.0f);

    // block-aggregated slot assignment (one atomic per block, 16 boxes)
    if (hl == 0) s_pref[wid * 2 + half] = present ? 1 : 0;
    __syncthreads();
    if (threadIdx.x == 0) {
        int run = 0;
#pragma unroll
        for (int i = 0; i < 16; i++) { int v = s_pref[i]; s_pref[i] = run; run += v; }
        s_base = atomicAdd(&g_cnt, run);
    }
    __syncthreads();
    int slot = s_base + s_pref[wid * 2 + half];

    int m  = grp * 2 + half;
    int bI = grp / GPB;
    int rI = m - bI * 1200;
    float* orow = out + ((size_t)bI * RPB + 600 + rI) * 512;

    if (present) {
        float w  = x2 - x1, hh = y2 - y1;
        float cx = (x1 + x2) * 0.5f, cy = (y1 + y2) * 0.5f;
        float area = w * hh;
        float asp  = w / (hh + 1e-6f);
        float ge[10] = {x1, y1, x2, y2, w, hh, cx, cy, area, asp};

        int d0 = hl * 16;
        float pre[16];
#pragma unroll
        for (int c = 0; c < 4; c++) {
            float4 a = *(const float4*)(b1 + d0 + c * 4);
            pre[c*4+0] = a.x; pre[c*4+1] = a.y; pre[c*4+2] = a.z; pre[c*4+3] = a.w;
        }
#pragma unroll
        for (int k = 0; k < 10; k++) {
            float gk = ge[k];
            const float* wr = w1 + k * 256 + d0;
#pragma unroll
            for (int c = 0; c < 4; c++) {
                float4 wv = __ldg((const float4*)(wr + c * 4));
                pre[c*4+0] = fmaf(gk, wv.x, pre[c*4+0]);
                pre[c*4+1] = fmaf(gk, wv.y, pre[c*4+1]);
                pre[c*4+2] = fmaf(gk, wv.z, pre[c*4+2]);
                pre[c*4+3] = fmaf(gk, wv.w, pre[c*4+3]);
            }
        }
        float s = 0.0f;
#pragma unroll
        for (int i = 0; i < 16; i++) s += pre[i];
#pragma unroll
        for (int o = 8; o > 0; o >>= 1) s += __shfl_xor_sync(0xffffffffu, s, o);
        float mu = s * (1.0f / 256.0f);
        float v = 0.0f;
#pragma unroll
        for (int i = 0; i < 16; i++) { float dd = pre[i] - mu; v = fmaf(dd, dd, v); }
#pragma unroll
        for (int o = 8; o > 0; o >>= 1) v += __shfl_xor_sync(0xffffffffu, v, o);
        float inv = rsqrtf(v * (1.0f / 256.0f) + 1e-5f);

        uint32_t u[8];
#pragma unroll
        for (int c = 0; c < 4; c++) {
            float4 gv = *(const float4*)(lng + d0 + c * 4);
            float4 bv = *(const float4*)(lnb + d0 + c * 4);
            float gl[4];
#pragma unroll
            for (int j = 0; j < 4; j++) {
                float gg = (j==0)?gv.x:((j==1)?gv.y:((j==2)?gv.z:gv.w));
                float bb = (j==0)?bv.x:((j==1)?bv.y:((j==2)?bv.z:bv.w));
                float x = (pre[c*4+j] - mu) * inv * gg + bb;
                gl[j] = 0.5f * x * (1.0f + erff(x * 0.70710678118654752440f));
            }
            __half2 hA = __floats2half2_rn(gl[0], gl[1]);
            __half2 hB = __floats2half2_rn(gl[2], gl[3]);
            u[c*2]   = *(uint32_t*)&hA;
            u[c*2+1] = *(uint32_t*)&hB;
        }
        __half* arow = g_A + (size_t)slot * 256 + d0;
        *(uint4*)(arow)     = make_uint4(u[0], u[1], u[2], u[3]);
        *(uint4*)(arow + 8) = make_uint4(u[4], u[5], u[6], u[7]);

        if (hl == 0) {
            g_meta[slot] = make_float4((float)(m * 4 + (int)cat), cf, cx, cy);
        }
    } else {
        // missing: write missing_emb row directly (unscaled, per reference)
#pragma unroll
        for (int i = 0; i < 8; i++) {
            int n = i * 64 + hl * 4;
            *(float4*)(orow + n) = __ldg((const float4*)(missv + n));
        }
    }

    // dist token row (once per group; all 32 lanes participate)
    {
        float cxa = (c0x1 + c0x2) * 0.5f, cya = (c0y1 + c0y2) * 0.5f;
        float cxb = (c1x1 + c1x2) * 0.5f, cyb = (c1y1 + c1y2) * 0.5f;
        float dx = cxa - cxb, dy = cya - cyb;
        float dist = sqrtf(dx * dx + dy * dy);
        float* drow = out + ((size_t)bI * RPB + (grp - bI * GPB)) * 512;
#pragma unroll
        for (int i = 0; i < 4; i++) {
            int n = i * 128 + lane * 4;
            float4 wv = __ldg((const float4*)(dw + n));
            float4 bv = __ldg((const float4*)(db + n));
            *(float4*)(drow + n) = make_float4(fmaf(dist, wv.x, bv.x), fmaf(dist, wv.y, bv.y),
                                               fmaf(dist, wv.z, bv.z), fmaf(dist, wv.w, bv.w));
        }
    }
}

// ============================================================
// Kernel G: fp16 mma.sync GEMM [count,256]x[256,512] on
// compacted rows + fused epilogue. BM=128, BN=128, BK=32,
// 8 warps, 4-stage cp.async pipeline. Fixed grid; early-exit.
// ============================================================
#define STAGES     4
#define TILE_ELEMS (128 * 40)
#define TILE_BYTES (TILE_ELEMS * 2)            // 10240
#define SMEM_GEMM  (2 * STAGES * TILE_BYTES)   // 81920
#define NCHUNKS    8                           // K = 256 / 32

__global__ void __launch_bounds__(256, 2) gemm_kernel(
    const float* __restrict__ scale_p, float* __restrict__ out)
{
    int count = g_cnt;
    int m0 = blockIdx.y * 128;
    if (m0 >= count) return;

    extern __shared__ __half smem_dyn[];
    uint32_t sbase = smem_u32(smem_dyn);
    uint32_t sbb   = sbase + STAGES * TILE_BYTES;

    int tid = threadIdx.x;
    int n0 = blockIdx.x * 128;
    int warp = tid >> 5, lane = tid & 31;
    int wm = warp >> 1, wn = warp & 1;

    int ldrow = tid >> 2, ldkc = (tid & 3) * 8;
    uint32_t aoff  = (uint32_t)(ldrow * 40 + ldkc) * 2;
    uint32_t aoff2 = (uint32_t)((ldrow + 64) * 40 + ldkc) * 2;

    float acc[2][8][4];
#pragma unroll
    for (int i = 0; i < 2; i++)
#pragma unroll
        for (int j = 0; j < 8; j++)
#pragma unroll
            for (int v = 0; v < 4; v++) acc[i][j][v] = 0.0f;

    int arow  = wm * 32 + (lane & 15);
    int acol8 = (lane >> 4) * 8;
    int brow  = wn * 64 + (lane & 7) + (lane >> 4) * 8;
    int bcol8 = ((lane >> 3) & 1) * 8;
    uint32_t a_base0 = sbase + (uint32_t)(arow * 40 + acol8) * 2;
    uint32_t a_base1 = sbase + (uint32_t)((arow + 16) * 40 + acol8) * 2;
    uint32_t b_base  = sbb   + (uint32_t)(brow * 40 + bcol8) * 2;

#define LOAD_STAGE(c, s) do {                                                    \
    const __half* gA = g_A + (size_t)(m0 + ldrow) * 256 + (c) * 32 + ldkc;       \
    const __half* gB = g_B + (size_t)(n0 + ldrow) * 256 + (c) * 32 + ldkc;       \
    uint32_t sA = sbase + (uint32_t)(s) * TILE_BYTES;                            \
    uint32_t sB = sbb   + (uint32_t)(s) * TILE_BYTES;                            \
    cpasync16(sA + aoff,  gA);                                                   \
    cpasync16(sA + aoff2, gA + (size_t)64 * 256);                                \
    cpasync16(sB + aoff,  gB);                                                   \
    cpasync16(sB + aoff2, gB + (size_t)64 * 256);                                \
    CP_COMMIT();                                                                 \
} while (0)

    LOAD_STAGE(0, 0);
    LOAD_STAGE(1, 1);
    LOAD_STAGE(2, 2);

#pragma unroll
    for (int c = 0; c < NCHUNKS; c++) {
        int s = c & 3;
        if (c < NCHUNKS - 2)       CP_WAIT(2);
        else if (c == NCHUNKS - 2) CP_WAIT(1);
        else                       CP_WAIT(0);
        __syncthreads();

        if (c + 3 < NCHUNKS) LOAD_STAGE(c + 3, (c + 3) & 3);

        uint32_t soff = (uint32_t)s * TILE_BYTES;
#pragma unroll
        for (int ks = 0; ks < 2; ks++) {
            uint32_t a[2][4], b[4][4];
            uint32_t kb = soff + ks * 32;
            ldm_x4(a[0], a_base0 + kb);
            ldm_x4(a[1], a_base1 + kb);
#pragma unroll
            for (int jp = 0; jp < 4; jp++)
                ldm_x4(b[jp], b_base + kb + (uint32_t)(jp * 16 * 40) * 2);
#pragma unroll
            for (int ti = 0; ti < 2; ti++)
#pragma unroll
                for (int jp = 0; jp < 4; jp++) {
                    mma16816(acc[ti][jp * 2],     a[ti], b[jp][0], b[jp][1]);
                    mma16816(acc[ti][jp * 2 + 1], a[ti], b[jp][2], b[jp][3]);
                }
        }
    }
#undef LOAD_STAGE

    // ---------------- epilogue ----------------
    float scl = __ldg(scale_p);
    int lane4 = lane >> 2;
    int colp  = (lane & 3) * 2;

#pragma unroll
    for (int ti = 0; ti < 2; ti++) {
        int rA = m0 + wm * 32 + ti * 16 + lane4;
        int rB = rA + 8;
        bool okA = (rA < count), okB = (rB < count);
        float4 mtA = okA ? g_meta[rA] : make_float4(0.0f, 0.0f, 0.0f, 0.0f);
        float4 mtB = okB ? g_meta[rB] : make_float4(0.0f, 0.0f, 0.0f, 0.0f);
        int qA = (int)mtA.x, qB = (int)mtB.x;
        int mA = qA >> 2,  mB = qB >> 2;
        int catA = qA & 3, catB = qB & 3;
        const float* eA = g_E + (size_t)(catA * 3 + ((mA >> 1) % 3)) * 512;
        const float* eB = g_E + (size_t)(catB * 3 + ((mB >> 1) % 3)) * 512;
        int bA = mA / 1200, rIA = mA - bA * 1200;
        int bB = mB / 1200, rIB = mB - bB * 1200;
        float* oA = out + ((size_t)bA * RPB + 600 + rIA) * 512;
        float* oB = out + ((size_t)bB * RPB + 600 + rIB) * 512;

#pragma unroll
        for (int j = 0; j < 8; j++) {
            int n = n0 + wn * 64 + j * 8 + colp;
            float4 t0 = g_T4[n], t1 = g_T4[n + 1];
            if (okA) {
                float v0 = (acc[ti][j][0] + eA[n]     + mtA.y * t0.x + mtA.z * t0.y + mtA.w * t0.z) * scl;
                float v1 = (acc[ti][j][1] + eA[n + 1] + mtA.y * t1.x + mtA.z * t1.y + mtA.w * t1.z) * scl;
                *(float2*)(oA + n) = make_float2(v0, v1);
            }
            if (okB) {
                float u0 = (acc[ti][j][2] + eB[n]     + mtB.y * t0.x + mtB.z * t0.y + mtB.w * t0.z) * scl;
                float u1 = (acc[ti][j][3] + eB[n + 1] + mtB.y * t1.x + mtB.z * t1.y + mtB.w * t1.z) * scl;
                *(float2*)(oB + n) = make_float2(u0, u1);
            }
        }
    }
}

// ============================================================
extern "C" void kernel_launch(void* const* d_in, const int* in_sizes, int n_in,
                              void* d_out, int out_size)
{
    const float* box   = (const float*)d_in[0];
    const float* catT  = (const float*)d_in[1];
    const float* w1    = (const float*)d_in[2];
    const float* b1    = (const float*)d_in[3];
    const float* lng   = (const float*)d_in[4];
    const float* lnb   = (const float*)d_in[5];
    const float* w2    = (const float*)d_in[6];
    const float* b2    = (const float*)d_in[7];
    const float* confw = (const float*)d_in[8];
    const float* confb = (const float*)d_in[9];
    const float* cw    = (const float*)d_in[10];
    const float* cb    = (const float*)d_in[11];
    const float* miss  = (const float*)d_in[12];
    const float* dw    = (const float*)d_in[13];
    const float* db    = (const float*)d_in[14];
    const float* cam   = (const float*)d_in[15];
    const float* scale = (const float*)d_in[16];
    float* out = (float*)d_out;

    cudaFuncSetAttribute(gemm_kernel, cudaFuncAttributeMaxDynamicSharedMemorySize, SMEM_GEMM);

    aux_kernel<<<523, 512>>>(w2, b2, catT, confw, confb, cw, cb, miss, cam);
    prep_kernel<<<NBOXES / 16, 256>>>(box, w1, b1, lng, lnb, dw, db, miss, out);

    dim3 grid(4, NBOXES / 128);   // fixed worst-case; blocks past count exit
    gemm_kernel<<<grid, 256, SMEM_GEMM>>>(scale, out);
}